// round 5
// baseline (speedup 1.0000x reference)
#include <cuda_runtime.h>

#define LOG2E 1.4426950408889634f
typedef unsigned long long u64;

// ---------------- f32x2 packed-math helpers (Blackwell dual-FP32) ----------
__device__ __forceinline__ u64 splat2(float x){
  u64 r; asm("mov.b64 %0, {%1,%1};" : "=l"(r) : "f"(x)); return r;
}
__device__ __forceinline__ u64 pack2(float a, float b){
  u64 r; asm("mov.b64 %0, {%1,%2};" : "=l"(r) : "f"(a), "f"(b)); return r;
}
__device__ __forceinline__ void unpack2(u64 v, float& a, float& b){
  asm("mov.b64 {%0,%1}, %2;" : "=f"(a), "=f"(b) : "l"(v));
}
__device__ __forceinline__ u64 ffma2(u64 a, u64 b, u64 c){
  u64 d; asm("fma.rn.f32x2 %0, %1, %2, %3;" : "=l"(d) : "l"(a), "l"(b), "l"(c));
  return d;
}
__device__ __forceinline__ u64 fmul2(u64 a, u64 b){
  u64 d; asm("mul.rn.f32x2 %0, %1, %2;" : "=l"(d) : "l"(a), "l"(b)); return d;
}
__device__ __forceinline__ float fexp2(float x){
  float y; asm("ex2.approx.ftz.f32 %0, %1;" : "=f"(y) : "f"(x)); return y;
}

// ---------------- scratch (device globals; no allocation allowed) ----------
__device__ float g_Q [8192*128];
__device__ float g_K [8192*128];
__device__ float g_V [8192*128];
__device__ float g_O [8192*128];
__device__ float g_Y [8192*128];
__device__ float g_FF[8192*512];
__device__ float g_red[2][8][2];   // [stage][sample][sum, sumsq]

// ---------------- GEMM microkernel: C[32][128], K=128, 256 thr -------------
// tr = tid>>5 owns 4 rows (tr*4..+3); lane owns cols lane*4..+3 (2 f32x2).
__device__ __forceinline__ void gemm_compute2(const float* As, const float* Ws,
                                              u64 acc[4][2], int r0, int lane){
  #pragma unroll
  for (int k4 = 0; k4 < 32; k4++){
    u64 b[4][2];
    #pragma unroll
    for (int j = 0; j < 4; j++){
      ulonglong2 bv = ((const ulonglong2*)Ws)[(k4*4+j)*32 + lane];
      b[j][0] = bv.x; b[j][1] = bv.y;
    }
    #pragma unroll
    for (int i = 0; i < 4; i++){
      float4 a = ((const float4*)As)[(r0+i)*32 + k4];
      u64 s0 = splat2(a.x), s1 = splat2(a.y), s2 = splat2(a.z), s3 = splat2(a.w);
      acc[i][0] = ffma2(s0, b[0][0], acc[i][0]);
      acc[i][1] = ffma2(s0, b[0][1], acc[i][1]);
      acc[i][0] = ffma2(s1, b[1][0], acc[i][0]);
      acc[i][1] = ffma2(s1, b[1][1], acc[i][1]);
      acc[i][0] = ffma2(s2, b[2][0], acc[i][0]);
      acc[i][1] = ffma2(s2, b[2][1], acc[i][1]);
      acc[i][0] = ffma2(s3, b[3][0], acc[i][0]);
      acc[i][1] = ffma2(s3, b[3][1], acc[i][1]);
    }
  }
}

__device__ __forceinline__ void ln_reduce_store(float s, float sq, float* sm,
                                                int tid, int b, int which){
  #pragma unroll
  for (int off = 16; off; off >>= 1){
    s  += __shfl_xor_sync(0xffffffffu, s,  off);
    sq += __shfl_xor_sync(0xffffffffu, sq, off);
  }
  __syncthreads();
  if ((tid & 31) == 0){ sm[tid>>5] = s; sm[8 + (tid>>5)] = sq; }
  __syncthreads();
  if (tid == 0){
    float S = 0.f, SQ = 0.f;
    #pragma unroll
    for (int w = 0; w < 8; w++){ S += sm[w]; SQ += sm[8+w]; }
    atomicAdd(&g_red[which][b][0], S);
    atomicAdd(&g_red[which][b][1], SQ);
  }
}

__device__ __forceinline__ void ln_params(int which, int b, float& mean, float& rstd){
  float s  = g_red[which][b][0];
  float sq = g_red[which][b][1];
  const float M = 131072.f;
  mean = s / M;
  float var = (sq - s*s/M) / (M - 1.f);
  rstd = rsqrtf(var + 1e-5f);
}

// ---------------- K1: QKV projections (+ zero g_red from block 0) ----------
__global__ void __launch_bounds__(256) qkv_kernel(const float* __restrict__ x,
    const float* __restrict__ Wq, const float* __restrict__ Wk,
    const float* __restrict__ Wv){
  extern __shared__ float sm[];
  float* As = sm;             // 32*128
  float* Ws = sm + 32*128;    // 128*128
  int row0 = blockIdx.x * 32;
  const float* W = (blockIdx.y==0) ? Wq : (blockIdx.y==1 ? Wk : Wv);
  float* outp    = (blockIdx.y==0) ? g_Q : (blockIdx.y==1 ? g_K : g_V);
  int tid = threadIdx.x;

  if (blockIdx.x == 0 && blockIdx.y == 0 && tid < 32)
    ((float*)g_red)[tid] = 0.f;

  #pragma unroll
  for (int rep = 0; rep < 4; rep++){
    int idx = rep*256 + tid;
    ((float4*)As)[idx] = ((const float4*)(x + (size_t)row0*128))[idx];
  }
  #pragma unroll
  for (int rep = 0; rep < 16; rep++){
    int idx = rep*256 + tid;               // Ws[e][j], j = h*32+k
    int e = idx >> 5, j4 = idx & 31;
    ((float4*)Ws)[idx] =
      *(const float4*)(W + ((j4>>3)<<12) + (e<<5) + ((j4&7)<<2));
  }
  __syncthreads();

  int tr = tid >> 5, lane = tid & 31;
  int r0 = tr*4, c0 = lane*4;
  u64 acc[4][2];
  #pragma unroll
  for (int i=0;i<4;i++){ acc[i][0]=splat2(0.f); acc[i][1]=splat2(0.f); }
  gemm_compute2(As, Ws, acc, r0, lane);
  #pragma unroll
  for (int i=0;i<4;i++){
    float c[4];
    unpack2(acc[i][0], c[0], c[1]); unpack2(acc[i][1], c[2], c[3]);
    *(float4*)(outp + (size_t)(row0+r0+i)*128 + c0) =
      make_float4(c[0],c[1],c[2],c[3]);
  }
}

// ---------------- K2: fused attention (512 threads) ------------------------
// grid (16, 8): blockIdx.x = 64-query tile, blockIdx.y = batch.
#define SM_STRIDE 68
__global__ void __launch_bounds__(512,1) attn_kernel(
    const float* __restrict__ in2, float* __restrict__ out2,
    const float* __restrict__ Ws1, const float* __restrict__ bs1,
    const float* __restrict__ Ws2, const float* __restrict__ bs2){
  extern __shared__ float sm[];
  float* Qs      = sm;              // 64*128 XOR-swizzled (16B granule)
  float* Ks      = Qs + 8192;       // 64*128 XOR-swizzled
  float* Vs      = Ks + 8192;       // 64*128 plain
  float* Smat    = Vs + 8192;       // 4*64*68
  float* alpha_s = Smat + 4*64*SM_STRIDE; // 256
  float* rsum_s  = alpha_s + 256;   // 256
  float* mw      = rsum_s + 256;    // 128 (8B-aligned base)

  int tid = threadIdx.x;
  int n0  = blockIdx.x * 64;
  int b   = blockIdx.y;

  if (tid < 64)       mw[tid] = Ws1[tid];
  else if (tid < 72)  mw[tid] = bs1[tid-64];
  else if (tid < 104) mw[tid] = Ws2[tid-72];
  else if (tid < 108) mw[tid] = bs2[tid-104];
  const u64* w1u = (const u64*)mw;        // [i*4+jp]
  const u64* b1u = (const u64*)(mw+64);   // [jp]
  const u64* w2u = (const u64*)(mw+72);   // row j -> 36-72.. at 2j,2j+1 rel
  const u64* b2u = (const u64*)(mw+104);

  // load Q tile (swizzle: k4 ^= (r>>3)&7)
  {
    const float* Qg = g_Q + ((size_t)(b*1024 + n0))*128;
    #pragma unroll
    for (int rep = 0; rep < 4; rep++){
      int idx = rep*512 + tid; int r = idx>>5, k4 = idx&31;
      float4 v = ((const float4*)Qg)[idx];
      *(float4*)(Qs + r*128 + ((k4 ^ ((r>>3)&7))<<2)) = v;
    }
  }

  int h = tid >> 7, t = tid & 127;
  int s_ni0 = (t&7)*8,  s_mi0 = (t>>3)*4;   // scores: 8 rows x 4 cols
  int p_ni0 = (t>>3)*4, p_k0  = (t&7)*4;    // PV: 4 rows x 4 cols
  int sm_row = tid >> 1, sm_half = tid & 1; // softmax: half-row per thread
  int m_ni = tid >> 3, m_mi0 = (tid&7)*8;   // MLP: 8 elems per thread

  u64 O2[4][2];
  #pragma unroll
  for (int i=0;i<4;i++){ O2[i][0]=splat2(0.f); O2[i][1]=splat2(0.f); }
  float rmax = -1e30f, rsum = 0.f;
  const u64 log2e2 = splat2(LOG2E);

  const float* in2b = in2  + (size_t)b*1048576;
  float*       o2b  = out2 + (size_t)b*1048576;

  for (int it = 0; it < 16; it++){
    int m0 = it*64;
    __syncthreads();   // prev PV / Smat reads done
    {
      const float* Kg = g_K + ((size_t)(b*1024 + m0))*128;
      const float* Vg = g_V + ((size_t)(b*1024 + m0))*128;
      #pragma unroll
      for (int rep = 0; rep < 4; rep++){
        int idx = rep*512 + tid; int r = idx>>5, k4 = idx&31;
        float4 kv = ((const float4*)Kg)[idx];
        *(float4*)(Ks + r*128 + ((k4 ^ ((r>>3)&7))<<2)) = kv;
        float4 vv = ((const float4*)Vg)[idx];
        *(float4*)(Vs + r*128 + (k4<<2)) = vv;
      }
    }
    __syncthreads();

    // ---- scores: 8x4 tile per thread, float4 operand loads ---------------
    {
      u64 acc2[8][2];
      #pragma unroll
      for (int i=0;i<8;i++){ acc2[i][0]=splat2(0.f); acc2[i][1]=splat2(0.f); }
      #pragma unroll
      for (int kk4 = 0; kk4 < 8; kk4++){
        int kidx = (h<<3) + kk4;
        float4 a4[8], b4[4];
        #pragma unroll
        for (int i=0;i<8;i++){
          int r = s_ni0 + i;
          a4[i] = *(const float4*)(Qs + r*128 + ((kidx ^ (r>>3))<<2));
        }
        #pragma unroll
        for (int j=0;j<4;j++){
          int r = s_mi0 + j;
          b4[j] = *(const float4*)(Ks + r*128 + ((kidx ^ (r>>3))<<2));
        }
        #pragma unroll
        for (int kk=0; kk<4; kk++){
          float bb0 = ((const float*)&b4[0])[kk];
          float bb1 = ((const float*)&b4[1])[kk];
          float bb2 = ((const float*)&b4[2])[kk];
          float bb3 = ((const float*)&b4[3])[kk];
          u64 bp0 = pack2(bb0, bb1);
          u64 bp1 = pack2(bb2, bb3);
          #pragma unroll
          for (int i=0;i<8;i++){
            u64 sa = splat2(((const float*)&a4[i])[kk]);
            acc2[i][0] = ffma2(sa, bp0, acc2[i][0]);
            acc2[i][1] = ffma2(sa, bp1, acc2[i][1]);
          }
        }
      }
      #pragma unroll
      for (int i=0;i<8;i++){
        float c[4];
        unpack2(acc2[i][0], c[0], c[1]); unpack2(acc2[i][1], c[2], c[3]);
        *(float4*)(Smat + ((h<<6) + s_ni0 + i)*SM_STRIDE + s_mi0) =
          make_float4(c[0],c[1],c[2],c[3]);
      }
    }
    __syncthreads();

    // ---- 8->8(relu)->4 MLP, fused input2 read + passthrough write --------
    {
      const float* p0 = in2b + ((size_t)(n0+m_ni)<<10) + m0 + m_mi0;
      float*       q0 = o2b  + ((size_t)(n0+m_ni)<<10) + m0 + m_mi0;
      float4 ta[4], tb[4];
      #pragma unroll
      for (int hh=0; hh<4; hh++){
        ta[hh] = *(const float4*)(p0 + (size_t)hh*8388608);
        tb[hh] = *(const float4*)(p0 + (size_t)hh*8388608 + 4);
        *(float4*)(q0 + (size_t)hh*8388608)     = ta[hh];
        *(float4*)(q0 + (size_t)hh*8388608 + 4) = tb[hh];
      }
      #pragma unroll
      for (int e=0; e<8; e++){
        int mi = m_mi0 + e;
        float x[8];
        #pragma unroll
        for (int hh=0; hh<4; hh++)
          x[hh] = Smat[((hh<<6)+m_ni)*SM_STRIDE + mi];
        #pragma unroll
        for (int hh=0; hh<4; hh++)
          x[4+hh] = (e<4) ? ((const float*)&ta[hh])[e]
                          : ((const float*)&tb[hh])[e-4];
        u64 z2[4] = { b1u[0], b1u[1], b1u[2], b1u[3] };
        #pragma unroll
        for (int i=0;i<8;i++){
          u64 sx = splat2(x[i]);
          #pragma unroll
          for (int jp=0;jp<4;jp++) z2[jp] = ffma2(sx, w1u[i*4+jp], z2[jp]);
        }
        u64 y2[2] = { b2u[0], b2u[1] };
        #pragma unroll
        for (int jp=0;jp<4;jp++){
          float zl, zh; unpack2(z2[jp], zl, zh);
          zl = fmaxf(zl, 0.f); zh = fmaxf(zh, 0.f);
          u64 sl = splat2(zl), sh = splat2(zh);
          int j0 = 2*jp, j1 = 2*jp+1;
          y2[0] = ffma2(sl, w2u[j0*2],   y2[0]);
          y2[1] = ffma2(sl, w2u[j0*2+1], y2[1]);
          y2[0] = ffma2(sh, w2u[j1*2],   y2[0]);
          y2[1] = ffma2(sh, w2u[j1*2+1], y2[1]);
        }
        y2[0] = fmul2(y2[0], log2e2);
        y2[1] = fmul2(y2[1], log2e2);
        float y[4];
        unpack2(y2[0], y[0], y[1]); unpack2(y2[1], y[2], y[3]);
        #pragma unroll
        for (int hh=0;hh<4;hh++)
          Smat[((hh<<6)+m_ni)*SM_STRIDE + mi] = y[hh];
      }
    }
    __syncthreads();

    // ---- online softmax: thread pair per row (shfl-combined) -------------
    {
      float* Sr = Smat + sm_row*SM_STRIDE + sm_half*32;
      float mt = -1e30f;
      #pragma unroll
      for (int q=0; q<16; q++){
        float2 v = *(const float2*)(Sr + 2*q);
        mt = fmaxf(mt, fmaxf(v.x, v.y));
      }
      float mo = __shfl_xor_sync(0xffffffffu, mt, 1);
      float mnew = fmaxf(rmax, fmaxf(mt, mo));
      float al = fexp2(rmax - mnew);
      float st = 0.f;
      #pragma unroll
      for (int q=0; q<16; q++){
        float2 v = *(const float2*)(Sr + 2*q);
        float p0 = fexp2(v.x - mnew);
        float p1 = fexp2(v.y - mnew);
        *(float2*)(Sr + 2*q) = make_float2(p0, p1);
        st += p0 + p1;
      }
      st += __shfl_xor_sync(0xffffffffu, st, 1);
      rsum = rsum*al + st;
      rmax = mnew;
      if (!sm_half){ alpha_s[sm_row] = al; rsum_s[sm_row] = rsum; }
    }
    __syncthreads();

    // ---- rescale + P @ V (4x4 tile, LDS.64 P pairs) ----------------------
    {
      #pragma unroll
      for (int i=0;i<4;i++){
        u64 al = splat2(alpha_s[(h<<6) + p_ni0 + i]);
        O2[i][0] = fmul2(O2[i][0], al);
        O2[i][1] = fmul2(O2[i][1], al);
      }
      const u64* prow0 = (const u64*)(Smat + ((h<<6)+p_ni0+0)*SM_STRIDE);
      const u64* prow1 = (const u64*)(Smat + ((h<<6)+p_ni0+1)*SM_STRIDE);
      const u64* prow2 = (const u64*)(Smat + ((h<<6)+p_ni0+2)*SM_STRIDE);
      const u64* prow3 = (const u64*)(Smat + ((h<<6)+p_ni0+3)*SM_STRIDE);
      const float* vbase = Vs + (h<<5) + p_k0;
      #pragma unroll 8
      for (int mi2 = 0; mi2 < 32; mi2++){
        u64 pp[4] = { prow0[mi2], prow1[mi2], prow2[mi2], prow3[mi2] };
        ulonglong2 vv0 = *(const ulonglong2*)(vbase + (2*mi2)*128);
        ulonglong2 vv1 = *(const ulonglong2*)(vbase + (2*mi2+1)*128);
        #pragma unroll
        for (int i=0;i<4;i++){
          float pa, pb; unpack2(pp[i], pa, pb);
          u64 s0 = splat2(pa), s1 = splat2(pb);
          O2[i][0] = ffma2(s0, vv0.x, O2[i][0]);
          O2[i][1] = ffma2(s0, vv0.y, O2[i][1]);
          O2[i][0] = ffma2(s1, vv1.x, O2[i][0]);
          O2[i][1] = ffma2(s1, vv1.y, O2[i][1]);
        }
      }
    }
  }

  // final normalize + write heads output
  float* Og = g_O + ((size_t)(b*1024 + n0))*128;
  #pragma unroll
  for (int i=0;i<4;i++){
    float inv = 1.f / rsum_s[(h<<6) + p_ni0 + i];
    float c[4];
    unpack2(O2[i][0], c[0], c[1]); unpack2(O2[i][1], c[2], c[3]);
    *(float4*)(Og + (size_t)(p_ni0+i)*128 + (h<<5) + p_k0) =
      make_float4(c[0]*inv, c[1]*inv, c[2]*inv, c[3]*inv);
  }
}

// ---------------- K3: out-projection + residual + LN sums ------------------
__global__ void __launch_bounds__(256) outproj_kernel(
    const float* __restrict__ input1, const float* __restrict__ Wout){
  extern __shared__ float sm[];
  float* As = sm; float* Ws = sm + 32*128;
  int row0 = blockIdx.x * 32; int tid = threadIdx.x;
  #pragma unroll
  for (int rep=0; rep<4; rep++){
    int idx = rep*256 + tid;
    ((float4*)As)[idx] = ((const float4*)(g_O + (size_t)row0*128))[idx];
  }
  #pragma unroll
  for (int rep=0; rep<16; rep++){
    int idx = rep*256 + tid;
    ((float4*)Ws)[idx] = ((const float4*)Wout)[idx];
  }
  __syncthreads();
  int tr = tid>>5, lane = tid&31, r0 = tr*4, c0 = lane*4;
  u64 acc[4][2];
  #pragma unroll
  for (int i=0;i<4;i++){ acc[i][0]=splat2(0.f); acc[i][1]=splat2(0.f); }
  gemm_compute2(As, Ws, acc, r0, lane);
  float s=0.f, sq=0.f;
  #pragma unroll
  for (int i=0;i<4;i++){
    float c[4];
    unpack2(acc[i][0], c[0], c[1]); unpack2(acc[i][1], c[2], c[3]);
    float4 res = *(const float4*)(input1 + (size_t)(row0+r0+i)*128 + c0);
    float4 o = make_float4(c[0]+res.x, c[1]+res.y, c[2]+res.z, c[3]+res.w);
    *(float4*)(g_Y + (size_t)(row0+r0+i)*128 + c0) = o;
    s  += o.x+o.y+o.z+o.w;
    sq += o.x*o.x+o.y*o.y+o.z*o.z+o.w*o.w;
  }
  ln_reduce_store(s, sq, sm, tid, row0>>10, 0);
}

// ---------------- K4: FF1 (inline LN of g_Y, relu) -------------------------
__global__ void __launch_bounds__(256) ff1_kernel(const float* __restrict__ Wff1){
  extern __shared__ float sm[];
  float* As = sm; float* Ws = sm + 32*128;
  int row0 = blockIdx.x * 32, ct = blockIdx.y, tid = threadIdx.x;
  float mean, rstd; ln_params(0, row0>>10, mean, rstd);
  #pragma unroll
  for (int rep=0; rep<4; rep++){
    int idx = rep*256 + tid;
    float4 v = ((const float4*)(g_Y + (size_t)row0*128))[idx];
    v.x=(v.x-mean)*rstd; v.y=(v.y-mean)*rstd;
    v.z=(v.z-mean)*rstd; v.w=(v.w-mean)*rstd;
    ((float4*)As)[idx] = v;
  }
  #pragma unroll
  for (int rep=0; rep<16; rep++){
    int idx = rep*256 + tid;
    int e = idx>>5, c4 = idx&31;
    ((float4*)Ws)[idx] = *(const float4*)(Wff1 + (size_t)e*512 + ct*128 + c4*4);
  }
  __syncthreads();
  int tr = tid>>5, lane = tid&31, r0 = tr*4, c0 = lane*4;
  u64 acc[4][2];
  #pragma unroll
  for (int i=0;i<4;i++){ acc[i][0]=splat2(0.f); acc[i][1]=splat2(0.f); }
  gemm_compute2(As, Ws, acc, r0, lane);
  #pragma unroll
  for (int i=0;i<4;i++){
    float c[4];
    unpack2(acc[i][0], c[0], c[1]); unpack2(acc[i][1], c[2], c[3]);
    float4 o = make_float4(fmaxf(c[0],0.f), fmaxf(c[1],0.f),
                           fmaxf(c[2],0.f), fmaxf(c[3],0.f));
    *(float4*)(g_FF + (size_t)(row0+r0+i)*512 + ct*128 + c0) = o;
  }
}

// ---------------- K5: FF2 + residual (inline LN of g_Y) + LN sums ----------
__global__ void __launch_bounds__(256) ff2_kernel(const float* __restrict__ Wff2){
  extern __shared__ float sm[];
  float* As = sm; float* Ws = sm + 32*128;
  int row0 = blockIdx.x * 32, tid = threadIdx.x;
  float mean, rstd; ln_params(0, row0>>10, mean, rstd);
  int tr = tid>>5, lane = tid&31, r0 = tr*4, c0 = lane*4;
  u64 acc[4][2];
  #pragma unroll
  for (int i=0;i<4;i++){ acc[i][0]=splat2(0.f); acc[i][1]=splat2(0.f); }
  for (int ch = 0; ch < 4; ch++){
    __syncthreads();
    #pragma unroll
    for (int rep=0; rep<4; rep++){
      int idx = rep*256 + tid; int r = idx>>5, k4 = idx&31;
      ((float4*)As)[idx] =
        *(const float4*)(g_FF + (size_t)(row0+r)*512 + ch*128 + k4*4);
    }
    #pragma unroll
    for (int rep=0; rep<16; rep++){
      int idx = rep*256 + tid;
      ((float4*)Ws)[idx] = ((const float4*)(Wff2 + (size_t)ch*16384))[idx];
    }
    __syncthreads();
    gemm_compute2(As, Ws, acc, r0, lane);
  }
  float s=0.f, sq=0.f;
  #pragma unroll
  for (int i=0;i<4;i++){
    float c[4];
    unpack2(acc[i][0], c[0], c[1]); unpack2(acc[i][1], c[2], c[3]);
    float4 res = *(const float4*)(g_Y + (size_t)(row0+r0+i)*128 + c0);
    res.x=(res.x-mean)*rstd; res.y=(res.y-mean)*rstd;
    res.z=(res.z-mean)*rstd; res.w=(res.w-mean)*rstd;
    float4 o = make_float4(c[0]+res.x, c[1]+res.y, c[2]+res.z, c[3]+res.w);
    *(float4*)(g_Y + (size_t)(row0+r0+i)*128 + c0) = o;
    s  += o.x+o.y+o.z+o.w;
    sq += o.x*o.x+o.y*o.y+o.z*o.z+o.w*o.w;
  }
  ln_reduce_store(s, sq, sm, tid, row0>>10, 1);
}

// NOTE: ff2 overwrites g_Y in place; safe because each CTA only rereads its
// own rows (normalized residual read happens before its own write, and no
// other CTA touches those rows).

// ---------------- K6: final global LayerNorm (ddof=1) ----------------------
__global__ void __launch_bounds__(256) norm_kernel(float* __restrict__ extout){
  int id = blockIdx.x*256 + threadIdx.x;          // float4 index
  int b = (id*4) >> 17;
  float mean, rstd; ln_params(1, b, mean, rstd);
  float4 v = ((const float4*)g_Y)[id];
  v.x = (v.x-mean)*rstd; v.y = (v.y-mean)*rstd;
  v.z = (v.z-mean)*rstd; v.w = (v.w-mean)*rstd;
  ((float4*)extout)[id] = v;
}

// ---------------- launcher --------------------------------------------------
extern "C" void kernel_launch(void* const* d_in, const int* in_sizes, int n_in,
                              void* d_out, int out_size){
  const float* input1 = (const float*)d_in[0];
  const float* input2 = (const float*)d_in[1];
  const float* Wq  = (const float*)d_in[2];
  const float* Wk  = (const float*)d_in[3];
  const float* Wv  = (const float*)d_in[4];
  const float* Wo  = (const float*)d_in[5];
  const float* Ws1 = (const float*)d_in[6];
  const float* bs1 = (const float*)d_in[7];
  const float* Ws2 = (const float*)d_in[8];
  const float* bs2 = (const float*)d_in[9];
  const float* Wff1 = (const float*)d_in[10];
  const float* Wff2 = (const float*)d_in[11];
  float* out1 = (float*)d_out;
  float* out2 = out1 + 8*1024*128;      // input2 passthrough region

  const int GEMM_SMEM = (32*128 + 128*128)*4;          // 81920
  const int ATTN_SMEM = (3*8192 + 4*64*SM_STRIDE + 256 + 256 + 128)*4; // 170496

  cudaFuncSetAttribute(qkv_kernel,     cudaFuncAttributeMaxDynamicSharedMemorySize, GEMM_SMEM);
  cudaFuncSetAttribute(attn_kernel,    cudaFuncAttributeMaxDynamicSharedMemorySize, ATTN_SMEM);
  cudaFuncSetAttribute(outproj_kernel, cudaFuncAttributeMaxDynamicSharedMemorySize, GEMM_SMEM);
  cudaFuncSetAttribute(ff1_kernel,     cudaFuncAttributeMaxDynamicSharedMemorySize, GEMM_SMEM);
  cudaFuncSetAttribute(ff2_kernel,     cudaFuncAttributeMaxDynamicSharedMemorySize, GEMM_SMEM);

  qkv_kernel<<<dim3(256,3), 256, GEMM_SMEM>>>(input1, Wq, Wk, Wv);
  attn_kernel<<<dim3(16,8), 512, ATTN_SMEM>>>(input2, out2, Ws1, bs1, Ws2, bs2);
  outproj_kernel<<<256, 256, GEMM_SMEM>>>(input1, Wo);
  ff1_kernel<<<dim3(256,4), 256, GEMM_SMEM>>>(Wff1);
  ff2_kernel<<<256, 256, GEMM_SMEM>>>(Wff2);
  norm_kernel<<<1024, 256>>>(out1);
}

// round 8
// speedup vs baseline: 1.2370x; 1.2370x over previous
#include <cuda_runtime.h>

#define LOG2E 1.4426950408889634f
typedef unsigned long long u64;

// ---------------- f32x2 packed-math helpers (Blackwell dual-FP32) ----------
__device__ __forceinline__ u64 splat2(float x){
  u64 r; asm("mov.b64 %0, {%1,%1};" : "=l"(r) : "f"(x)); return r;
}
__device__ __forceinline__ u64 pack2(float a, float b){
  u64 r; asm("mov.b64 %0, {%1,%2};" : "=l"(r) : "f"(a), "f"(b)); return r;
}
__device__ __forceinline__ void unpack2(u64 v, float& a, float& b){
  asm("mov.b64 {%0,%1}, %2;" : "=f"(a), "=f"(b) : "l"(v));
}
__device__ __forceinline__ u64 ffma2(u64 a, u64 b, u64 c){
  u64 d; asm("fma.rn.f32x2 %0, %1, %2, %3;" : "=l"(d) : "l"(a), "l"(b), "l"(c));
  return d;
}
__device__ __forceinline__ u64 fmul2(u64 a, u64 b){
  u64 d; asm("mul.rn.f32x2 %0, %1, %2;" : "=l"(d) : "l"(a), "l"(b)); return d;
}
__device__ __forceinline__ float fexp2(float x){
  float y; asm("ex2.approx.ftz.f32 %0, %1;" : "=f"(y) : "f"(x)); return y;
}

// ---------------- scratch (device globals; no allocation allowed) ----------
__device__ float g_Q [8192*128];
__device__ float g_K [8192*128];
__device__ float g_V [8192*128];
__device__ float g_Y [8192*128];
__device__ float g_FF[8192*512];
__device__ float g_red[2][8][2];   // [stage][sample][sum, sumsq]

// ---------------- GEMM microkernel: C[64][128], K-chunk=128, 256 thr -------
// tr = tid>>5 owns rows tr*8..+7; lane owns cols lane*4..+3 (2 f32x2 pairs).
// A loads are warp-broadcast (N=1), B loads lane-spread conflict-free.
__device__ __forceinline__ void gemm_compute2(const float* As, const float* Ws,
                                              u64 acc[8][2], int r0, int lane){
  #pragma unroll
  for (int k4 = 0; k4 < 32; k4++){
    u64 b[4][2];
    #pragma unroll
    for (int j = 0; j < 4; j++){
      ulonglong2 bv = ((const ulonglong2*)Ws)[(k4*4+j)*32 + lane];
      b[j][0] = bv.x; b[j][1] = bv.y;
    }
    #pragma unroll
    for (int i = 0; i < 8; i++){
      float4 a = ((const float4*)As)[(r0+i)*32 + k4];
      u64 s0 = splat2(a.x), s1 = splat2(a.y), s2 = splat2(a.z), s3 = splat2(a.w);
      acc[i][0] = ffma2(s0, b[0][0], acc[i][0]);
      acc[i][1] = ffma2(s0, b[0][1], acc[i][1]);
      acc[i][0] = ffma2(s1, b[1][0], acc[i][0]);
      acc[i][1] = ffma2(s1, b[1][1], acc[i][1]);
      acc[i][0] = ffma2(s2, b[2][0], acc[i][0]);
      acc[i][1] = ffma2(s2, b[2][1], acc[i][1]);
      acc[i][0] = ffma2(s3, b[3][0], acc[i][0]);
      acc[i][1] = ffma2(s3, b[3][1], acc[i][1]);
    }
  }
}

__device__ __forceinline__ void ln_reduce_store(float s, float sq, float* sm,
                                                int tid, int b, int which){
  #pragma unroll
  for (int off = 16; off; off >>= 1){
    s  += __shfl_xor_sync(0xffffffffu, s,  off);
    sq += __shfl_xor_sync(0xffffffffu, sq, off);
  }
  __syncthreads();
  if ((tid & 31) == 0){ sm[tid>>5] = s; sm[8 + (tid>>5)] = sq; }
  __syncthreads();
  if (tid == 0){
    float S = 0.f, SQ = 0.f;
    #pragma unroll
    for (int w = 0; w < 8; w++){ S += sm[w]; SQ += sm[8+w]; }
    atomicAdd(&g_red[which][b][0], S);
    atomicAdd(&g_red[which][b][1], SQ);
  }
}

__device__ __forceinline__ void ln_params(int which, int b, float& mean, float& rstd){
  float s  = g_red[which][b][0];
  float sq = g_red[which][b][1];
  const float M = 131072.f;
  mean = s / M;
  float var = (sq - s*s/M) / (M - 1.f);
  rstd = rsqrtf(var + 1e-5f);
}

// ---------------- K1: QKV projections (+ zero g_red from block (0,0)) ------
__global__ void __launch_bounds__(256) qkv_kernel(const float* __restrict__ x,
    const float* __restrict__ Wq, const float* __restrict__ Wk,
    const float* __restrict__ Wv){
  extern __shared__ float sm[];
  float* As = sm;             // 64*128
  float* Ws = sm + 64*128;    // 128*128
  int row0 = blockIdx.x * 64;
  const float* W = (blockIdx.y==0) ? Wq : (blockIdx.y==1 ? Wk : Wv);
  float* outp    = (blockIdx.y==0) ? g_Q : (blockIdx.y==1 ? g_K : g_V);
  int tid = threadIdx.x;

  if (blockIdx.x == 0 && blockIdx.y == 0 && tid < 32)
    ((float*)g_red)[tid] = 0.f;

  #pragma unroll
  for (int rep = 0; rep < 8; rep++){
    int idx = rep*256 + tid;
    ((float4*)As)[idx] = ((const float4*)(x + (size_t)row0*128))[idx];
  }
  #pragma unroll
  for (int rep = 0; rep < 16; rep++){
    int idx = rep*256 + tid;               // Ws[e][j], j = h*32+k
    int e = idx >> 5, j4 = idx & 31;
    ((float4*)Ws)[idx] =
      *(const float4*)(W + ((j4>>3)<<12) + (e<<5) + ((j4&7)<<2));
  }
  __syncthreads();

  int tr = tid >> 5, lane = tid & 31;
  int r0 = tr*8, c0 = lane*4;
  u64 acc[8][2];
  #pragma unroll
  for (int i=0;i<8;i++){ acc[i][0]=splat2(0.f); acc[i][1]=splat2(0.f); }
  gemm_compute2(As, Ws, acc, r0, lane);
  #pragma unroll
  for (int i=0;i<8;i++){
    float c[4];
    unpack2(acc[i][0], c[0], c[1]); unpack2(acc[i][1], c[2], c[3]);
    *(float4*)(outp + (size_t)(row0+r0+i)*128 + c0) =
      make_float4(c[0],c[1],c[2],c[3]);
  }
}

// ---------------- K2: fused attention + out-projection + residual + LN0 ----
// grid (16, 8): blockIdx.x = 64-query tile, blockIdx.y = batch. 256 threads.
__global__ void __launch_bounds__(256,1) attn_kernel(
    const float* __restrict__ in2, float* __restrict__ out2,
    const float* __restrict__ Ws1, const float* __restrict__ bs1,
    const float* __restrict__ Ws2, const float* __restrict__ bs2,
    const float* __restrict__ input1, const float* __restrict__ Wout){
  extern __shared__ float sm[];
  float* Qs      = sm;             // 64*128 XOR-swizzled (16B granule)
  float* Ks      = Qs + 8192;      // 64*128 XOR-swizzled
  float* Vs      = Ks + 8192;      // 64*128 plain
  float* Smat    = Vs + 8192;      // 4*64*65
  float* alpha_s = Smat + 4*64*65; // 256
  float* rsum_s  = alpha_s + 256;  // 256
  float* mw      = rsum_s + 256;   // 112

  int tid = threadIdx.x;
  int n0  = blockIdx.x * 64;
  int b   = blockIdx.y;

  if (tid < 64)       mw[tid] = Ws1[tid];
  else if (tid < 72)  mw[tid] = bs1[tid-64];
  else if (tid < 104) mw[tid] = Ws2[tid-72];
  else if (tid < 108) mw[tid] = bs2[tid-104];

  // MLP layer-1 weights in registers (smem-limited occupancy, regs free)
  u64 w1[8][4], b1[4];
  #pragma unroll
  for (int i=0;i<8;i++)
    #pragma unroll
    for (int jp=0;jp<4;jp++)
      w1[i][jp] = *(const u64*)(Ws1 + i*8 + 2*jp);
  #pragma unroll
  for (int jp=0;jp<4;jp++) b1[jp] = *(const u64*)(bs1 + 2*jp);

  // load Q tile (swizzled: k4 ^= (r>>3)&7)
  {
    const float* Qg = g_Q + ((size_t)(b*1024 + n0))*128;
    #pragma unroll
    for (int rep = 0; rep < 8; rep++){
      int idx = rep*256 + tid; int r = idx>>5, k4 = idx&31;
      float4 v = ((const float4*)Qg)[r*32 + k4];
      *(float4*)(Qs + r*128 + ((k4 ^ ((r>>3)&7))<<2)) = v;
    }
  }

  int h = tid >> 6, t = tid & 63;
  int s_ni0 = (t&7)*8, s_mi0 = (t>>3)*8;      // score micro-tile 8x8
  int p_ni0 = (t>>3)*8, p_k0  = (t&7)*4;      // PV / output micro-tile
  int qsw = t & 7, ksw = t >> 3;

  u64 O2[8][2];
  #pragma unroll
  for (int i=0;i<8;i++){ O2[i][0]=splat2(0.f); O2[i][1]=splat2(0.f); }
  float rmax = -1e30f, rsum = 0.f;

  const float* in2b = in2  + (size_t)b*1048576;
  float*       o2b  = out2 + (size_t)b*1048576;

  // pipeline: preload K tile 0 into registers
  float4 kreg[8];
  {
    const float* Kg = g_K + ((size_t)(b*1024))*128;
    #pragma unroll
    for (int rep = 0; rep < 8; rep++) kreg[rep] = ((const float4*)Kg)[rep*256 + tid];
  }

  for (int it = 0; it < 16; it++){
    int m0 = it*64;
    __syncthreads();   // prev PV / Smat reads done before overwriting Ks/Vs/Smat
    // store preloaded K -> smem (swizzled)
    #pragma unroll
    for (int rep = 0; rep < 8; rep++){
      int idx = rep*256 + tid; int r = idx>>5, k4 = idx&31;
      *(float4*)(Ks + r*128 + ((k4 ^ ((r>>3)&7))<<2)) = kreg[rep];
    }
    // issue V loads now; STS deferred until after scores (latency hidden)
    float4 vreg[8];
    {
      const float* Vg = g_V + ((size_t)(b*1024 + m0))*128;
      #pragma unroll
      for (int rep = 0; rep < 8; rep++) vreg[rep] = ((const float4*)Vg)[rep*256 + tid];
    }
    __syncthreads();   // Ks visible

    // ---- scores: S[h][ni][mi] = Q_h . K_h (f32x2, cols packed) ----------
    {
      u64 acc2[8][4];
      #pragma unroll
      for (int i=0;i<8;i++)
        #pragma unroll
        for (int jp=0;jp<4;jp++) acc2[i][jp] = splat2(0.f);
      int kb = h << 5;
      #pragma unroll
      for (int kk = 0; kk < 32; kk++){
        int k = kb + kk, kidx = k >> 2, kl = k & 3;
        float a[8], bb[8];
        #pragma unroll
        for (int i=0;i<8;i++)
          a[i]  = Qs[(s_ni0+i)*128 + ((kidx ^ qsw)<<2) + kl];
        #pragma unroll
        for (int j=0;j<8;j++)
          bb[j] = Ks[(s_mi0+j)*128 + ((kidx ^ ksw)<<2) + kl];
        u64 bp[4];
        #pragma unroll
        for (int jp=0;jp<4;jp++) bp[jp] = pack2(bb[2*jp], bb[2*jp+1]);
        #pragma unroll
        for (int i=0;i<8;i++){
          u64 sa = splat2(a[i]);
          #pragma unroll
          for (int jp=0;jp<4;jp++) acc2[i][jp] = ffma2(sa, bp[jp], acc2[i][jp]);
        }
      }
      #pragma unroll
      for (int i=0;i<8;i++){
        float* Sr = Smat + ((h<<6) + s_ni0 + i)*65 + s_mi0;
        float c[8];
        #pragma unroll
        for (int jp=0;jp<4;jp++) unpack2(acc2[i][jp], c[2*jp], c[2*jp+1]);
        #pragma unroll
        for (int j=0;j<8;j++) Sr[j] = c[j];
      }
    }

    // store V -> smem (needed only in PV; ordered by the sync below)
    #pragma unroll
    for (int rep = 0; rep < 8; rep++){
      int idx = rep*256 + tid; int r = idx>>5, k4 = idx&31;
      *(float4*)(Vs + r*128 + (k4<<2)) = vreg[rep];
    }
    // preload next K tile (consumed after next loop-top sync)
    if (it < 15){
      const float* Kg = g_K + ((size_t)(b*1024 + m0 + 64))*128;
      #pragma unroll
      for (int rep = 0; rep < 8; rep++) kreg[rep] = ((const float4*)Kg)[rep*256 + tid];
    }
    __syncthreads();   // Smat + Vs visible

    // ---- 8->8(relu)->4 MLP (f32x2), fused input2 read + passthrough -----
    {
      int ni  = tid >> 2;
      int mi0 = (tid & 3) * 4;
      const float* p0 = in2b + ((size_t)(n0+ni)<<10) + m0;
      float*       q0 = o2b  + ((size_t)(n0+ni)<<10) + m0;
      #pragma unroll
      for (int m4 = 0; m4 < 4; m4++){
        int mbase = mi0 + m4*16;
        float4 t2[4];
        #pragma unroll
        for (int hh=0; hh<4; hh++){
          t2[hh] = *(const float4*)(p0 + (size_t)hh*8388608 + mbase);
          *(float4*)(q0 + (size_t)hh*8388608 + mbase) = t2[hh];
        }
        #pragma unroll
        for (int e=0; e<4; e++){
          int mi = mbase + e;
          float x[8];
          #pragma unroll
          for (int hh=0; hh<4; hh++) x[hh] = Smat[((hh<<6)+ni)*65 + mi];
          x[4] = ((float*)&t2[0])[e]; x[5] = ((float*)&t2[1])[e];
          x[6] = ((float*)&t2[2])[e]; x[7] = ((float*)&t2[3])[e];
          u64 z2[4] = { b1[0], b1[1], b1[2], b1[3] };
          #pragma unroll
          for (int i=0;i<8;i++){
            u64 sx = splat2(x[i]);
            #pragma unroll
            for (int jp=0;jp<4;jp++) z2[jp] = ffma2(sx, w1[i][jp], z2[jp]);
          }
          u64 y2[2] = { *(const u64*)(mw+32+72-32), *(const u64*)(mw+104+2-2+102-100) };
          // (rewritten clearly below)
          y2[0] = *(const u64*)(mw+104);
          y2[1] = *(const u64*)(mw+106);
          #pragma unroll
          for (int jp=0;jp<4;jp++){
            float zl, zh; unpack2(z2[jp], zl, zh);
            zl = fmaxf(zl, 0.f); zh = fmaxf(zh, 0.f);
            u64 sl = splat2(zl), sh = splat2(zh);
            int j0 = 2*jp, j1 = 2*jp+1;
            y2[0] = ffma2(sl, *(const u64*)(mw + 72 + j0*4),     y2[0]);
            y2[1] = ffma2(sl, *(const u64*)(mw + 72 + j0*4 + 2), y2[1]);
            y2[0] = ffma2(sh, *(const u64*)(mw + 72 + j1*4),     y2[0]);
            y2[1] = ffma2(sh, *(const u64*)(mw + 72 + j1*4 + 2), y2[1]);
          }
          float y[4];
          unpack2(y2[0], y[0], y[1]); unpack2(y2[1], y[2], y[3]);
          #pragma unroll
          for (int hh=0;hh<4;hh++) Smat[((hh<<6)+ni)*65 + mi] = y[hh]*LOG2E;
        }
      }
    }
    __syncthreads();

    // ---- online softmax (1 thread per (h,ni) row) -----------------------
    {
      float* Sr = Smat + tid*65;
      float mt = -1e30f;
      #pragma unroll 8
      for (int mi=0; mi<64; mi++) mt = fmaxf(mt, Sr[mi]);
      float mnew = fmaxf(rmax, mt);
      float al = fexp2(rmax - mnew);
      float st = 0.f;
      #pragma unroll 8
      for (int mi=0; mi<64; mi++){
        float p = fexp2(Sr[mi] - mnew);
        Sr[mi] = p; st += p;
      }
      rsum = rsum*al + st;
      rmax = mnew;
      alpha_s[tid] = al;
      rsum_s[tid]  = rsum;
    }
    __syncthreads();

    // ---- rescale + P @ V (f32x2) ----------------------------------------
    {
      #pragma unroll
      for (int i=0;i<8;i++){
        u64 al = splat2(alpha_s[(h<<6) + p_ni0 + i]);
        O2[i][0] = fmul2(O2[i][0], al);
        O2[i][1] = fmul2(O2[i][1], al);
      }
      #pragma unroll 8
      for (int mi=0; mi<64; mi++){
        ulonglong2 vv =
          *(const ulonglong2*)(Vs + mi*128 + (h<<5) + p_k0);
        float p[8];
        #pragma unroll
        for (int i=0;i<8;i++) p[i] = Smat[((h<<6)+p_ni0+i)*65 + mi];
        #pragma unroll
        for (int i=0;i<8;i++){
          u64 sp = splat2(p[i]);
          O2[i][0] = ffma2(sp, vv.x, O2[i][0]);
          O2[i][1] = ffma2(sp, vv.y, O2[i][1]);
        }
      }
    }
  }

  // ---- fused out-projection epilogue -------------------------------------
  // 1) normalized O tile -> Qs (plain layout)
  __syncthreads();   // all Smat/Vs reads complete; smem reusable
  #pragma unroll
  for (int i=0;i<8;i++){
    float inv = 1.f / rsum_s[(h<<6) + p_ni0 + i];
    float c[4];
    unpack2(O2[i][0], c[0], c[1]); unpack2(O2[i][1], c[2], c[3]);
    *(float4*)(Qs + (p_ni0+i)*128 + (h<<5) + p_k0) =
      make_float4(c[0]*inv, c[1]*inv, c[2]*inv, c[3]*inv);
  }
  // 2) W_out -> Ks..Vs region (64 KB, direct [j][e] copy)
  float* Wsm = Ks;
  #pragma unroll
  for (int rep=0; rep<16; rep++){
    int idx = rep*256 + tid;
    ((float4*)Wsm)[idx] = ((const float4*)Wout)[idx];
  }
  __syncthreads();
  // 3) C = O @ Wout ; + residual ; -> g_Y ; LN stage-0 partial sums
  {
    int tr = tid>>5, lane = tid&31, r0 = tr*8, c0 = lane*4;
    u64 acc[8][2];
    #pragma unroll
    for (int i=0;i<8;i++){ acc[i][0]=splat2(0.f); acc[i][1]=splat2(0.f); }
    gemm_compute2(Qs, Wsm, acc, r0, lane);
    float s=0.f, sq=0.f;
    size_t grow0 = (size_t)(b*1024 + n0);
    #pragma unroll
    for (int i=0;i<8;i++){
      float c[4];
      unpack2(acc[i][0], c[0], c[1]); unpack2(acc[i][1], c[2], c[3]);
      float4 res = *(const float4*)(input1 + (grow0+r0+i)*128 + c0);
      float4 o = make_float4(c[0]+res.x, c[1]+res.y, c[2]+res.z, c[3]+res.w);
      *(float4*)(g_Y + (grow0+r0+i)*128 + c0) = o;
      s  += o.x+o.y+o.z+o.w;
      sq += o.x*o.x+o.y*o.y+o.z*o.z+o.w*o.w;
    }
    ln_reduce_store(s, sq, sm, tid, b, 0);
  }
}

// ---------------- K3: FF1 (inline LN0 of g_Y, relu) ------------------------
__global__ void __launch_bounds__(256) ff1_kernel(const float* __restrict__ Wff1){
  extern __shared__ float sm[];
  float* As = sm; float* Ws = sm + 64*128;
  int row0 = blockIdx.x * 64, ct = blockIdx.y, tid = threadIdx.x;
  float mean, rstd; ln_params(0, row0>>10, mean, rstd);
  #pragma unroll
  for (int rep=0; rep<8; rep++){
    int idx = rep*256 + tid;
    float4 v = ((const float4*)(g_Y + (size_t)row0*128))[idx];
    v.x=(v.x-mean)*rstd; v.y=(v.y-mean)*rstd;
    v.z=(v.z-mean)*rstd; v.w=(v.w-mean)*rstd;
    ((float4*)As)[idx] = v;
  }
  #pragma unroll
  for (int rep=0; rep<16; rep++){
    int idx = rep*256 + tid;
    int e = idx>>5, c4 = idx&31;
    ((float4*)Ws)[idx] = *(const float4*)(Wff1 + (size_t)e*512 + ct*128 + c4*4);
  }
  __syncthreads();
  int tr = tid>>5, lane = tid&31, r0 = tr*8, c0 = lane*4;
  u64 acc[8][2];
  #pragma unroll
  for (int i=0;i<8;i++){ acc[i][0]=splat2(0.f); acc[i][1]=splat2(0.f); }
  gemm_compute2(As, Ws, acc, r0, lane);
  #pragma unroll
  for (int i=0;i<8;i++){
    float c[4];
    unpack2(acc[i][0], c[0], c[1]); unpack2(acc[i][1], c[2], c[3]);
    float4 o = make_float4(fmaxf(c[0],0.f), fmaxf(c[1],0.f),
                           fmaxf(c[2],0.f), fmaxf(c[3],0.f));
    *(float4*)(g_FF + (size_t)(row0+r0+i)*512 + ct*128 + c0) = o;
  }
}

// ---------------- K4: FF2 + residual (inline LN0 of g_Y) + LN1 sums --------
__global__ void __launch_bounds__(256) ff2_kernel(const float* __restrict__ Wff2){
  extern __shared__ float sm[];
  float* As = sm; float* Ws = sm + 64*128;
  int row0 = blockIdx.x * 64, tid = threadIdx.x;
  float mean, rstd; ln_params(0, row0>>10, mean, rstd);
  int tr = tid>>5, lane = tid&31, r0 = tr*8, c0 = lane*4;
  u64 acc[8][2];
  #pragma unroll
  for (int i=0;i<8;i++){ acc[i][0]=splat2(0.f); acc[i][1]=splat2(0.f); }
  for (int ch = 0; ch < 4; ch++){
    __syncthreads();
    #pragma unroll
    for (int rep=0; rep<8; rep++){
      int idx = rep*256 + tid; int r = idx>>5, k4 = idx&31;
      ((float4*)As)[idx] =
        *(const float4*)(g_FF + (size_t)(row0+r)*512 + ch*128 + k4*4);
    }
    #pragma unroll
    for (int rep=0; rep<16; rep++){
      int idx = rep*256 + tid;
      ((float4*)Ws)[idx] = ((const float4*)(Wff2 + (size_t)ch*16384))[idx];
    }
    __syncthreads();
    gemm_compute2(As, Ws, acc, r0, lane);
  }
  float s=0.f, sq=0.f;
  #pragma unroll
  for (int i=0;i<8;i++){
    float c[4];
    unpack2(acc[i][0], c[0], c[1]); unpack2(acc[i][1], c[2], c[3]);
    float4 res = *(const float4*)(g_Y + (size_t)(row0+r0+i)*128 + c0);
    res.x=(res.x-mean)*rstd; res.y=(res.y-mean)*rstd;
    res.z=(res.z-mean)*rstd; res.w=(res.w-mean)*rstd;
    float4 o = make_float4(c[0]+res.x, c[1]+res.y, c[2]+res.z, c[3]+res.w);
    *(float4*)(g_Y + (size_t)(row0+r0+i)*128 + c0) = o;   // in-place: own rows only
    s  += o.x+o.y+o.z+o.w;
    sq += o.x*o.x+o.y*o.y+o.z*o.z+o.w*o.w;
  }
  ln_reduce_store(s, sq, sm, tid, row0>>10, 1);
}

// ---------------- K5: final global LayerNorm (ddof=1) ----------------------
__global__ void __launch_bounds__(256) norm_kernel(float* __restrict__ extout){
  int id = blockIdx.x*256 + threadIdx.x;          // float4 index
  int b = (id*4) >> 17;
  float mean, rstd; ln_params(1, b, mean, rstd);
  float4 v = ((const float4*)g_Y)[id];
  v.x = (v.x-mean)*rstd; v.y = (v.y-mean)*rstd;
  v.z = (v.z-mean)*rstd; v.w = (v.w-mean)*rstd;
  ((float4*)extout)[id] = v;
}

// ---------------- launcher --------------------------------------------------
extern "C" void kernel_launch(void* const* d_in, const int* in_sizes, int n_in,
                              void* d_out, int out_size){
  const float* input1 = (const float*)d_in[0];
  const float* input2 = (const float*)d_in[1];
  const float* Wq  = (const float*)d_in[2];
  const float* Wk  = (const float*)d_in[3];
  const float* Wv  = (const float*)d_in[4];
  const float* Wo  = (const float*)d_in[5];
  const float* Ws1 = (const float*)d_in[6];
  const float* bs1 = (const float*)d_in[7];
  const float* Ws2 = (const float*)d_in[8];
  const float* bs2 = (const float*)d_in[9];
  const float* Wff1 = (const float*)d_in[10];
  const float* Wff2 = (const float*)d_in[11];
  float* out1 = (float*)d_out;
  float* out2 = out1 + 8*1024*128;      // input2 passthrough region

  const int GEMM_SMEM = (64*128 + 128*128)*4;                       // 98304
  const int ATTN_SMEM = (3*8192 + 4*64*65 + 256 + 256 + 112)*4;     // 167360

  cudaFuncSetAttribute(qkv_kernel,  cudaFuncAttributeMaxDynamicSharedMemorySize, GEMM_SMEM);
  cudaFuncSetAttribute(attn_kernel, cudaFuncAttributeMaxDynamicSharedMemorySize, ATTN_SMEM);
  cudaFuncSetAttribute(ff1_kernel,  cudaFuncAttributeMaxDynamicSharedMemorySize, GEMM_SMEM);
  cudaFuncSetAttribute(ff2_kernel,  cudaFuncAttributeMaxDynamicSharedMemorySize, GEMM_SMEM);

  qkv_kernel<<<dim3(128,3), 256, GEMM_SMEM>>>(input1, Wq, Wk, Wv);
  attn_kernel<<<dim3(16,8), 256, ATTN_SMEM>>>(input2, out2, Ws1, bs1, Ws2, bs2,
                                              input1, Wo);
  ff1_kernel<<<dim3(128,4), 256, GEMM_SMEM>>>(Wff1);
  ff2_kernel<<<128, 256, GEMM_SMEM>>>(Wff2);
  norm_kernel<<<1024, 256>>>(out1);
}

// round 10
// speedup vs baseline: 1.2393x; 1.0019x over previous
#include <cuda_runtime.h>

#define LOG2E 1.4426950408889634f
typedef unsigned long long u64;

// ---------------- f32x2 packed-math helpers (Blackwell dual-FP32) ----------
__device__ __forceinline__ u64 splat2(float x){
  u64 r; asm("mov.b64 %0, {%1,%1};" : "=l"(r) : "f"(x)); return r;
}
__device__ __forceinline__ u64 pack2(float a, float b){
  u64 r; asm("mov.b64 %0, {%1,%2};" : "=l"(r) : "f"(a), "f"(b)); return r;
}
__device__ __forceinline__ void unpack2(u64 v, float& a, float& b){
  asm("mov.b64 {%0,%1}, %2;" : "=f"(a), "=f"(b) : "l"(v));
}
__device__ __forceinline__ u64 ffma2(u64 a, u64 b, u64 c){
  u64 d; asm("fma.rn.f32x2 %0, %1, %2, %3;" : "=l"(d) : "l"(a), "l"(b), "l"(c));
  return d;
}
__device__ __forceinline__ u64 fmul2(u64 a, u64 b){
  u64 d; asm("mul.rn.f32x2 %0, %1, %2;" : "=l"(d) : "l"(a), "l"(b)); return d;
}
__device__ __forceinline__ float fexp2(float x){
  float y; asm("ex2.approx.ftz.f32 %0, %1;" : "=f"(y) : "f"(x)); return y;
}

// ---------------- scratch (device globals; no allocation allowed) ----------
__device__ float g_Q [8192*128];
__device__ float g_K [8192*128];
__device__ float g_V [8192*128];
__device__ float g_O [8192*128];
__device__ float g_Y [8192*128];
__device__ float g_FF[8192*512];
__device__ float g_red[2][8][2];   // [stage][sample][sum, sumsq]

// ---------------- GEMM microkernel: C[64][128], K-chunk=128, 256 thr -------
// tr = tid>>5 owns rows tr*8..+7; lane owns cols lane*4..+3 (2 f32x2 pairs).
__device__ __forceinline__ void gemm_compute2(const float* As, const float* Ws,
                                              u64 acc[8][2], int r0, int lane){
  #pragma unroll
  for (int k4 = 0; k4 < 32; k4++){
    u64 b[4][2];
    #pragma unroll
    for (int j = 0; j < 4; j++){
      ulonglong2 bv = ((const ulonglong2*)Ws)[(k4*4+j)*32 + lane];
      b[j][0] = bv.x; b[j][1] = bv.y;
    }
    #pragma unroll
    for (int i = 0; i < 8; i++){
      float4 a = ((const float4*)As)[(r0+i)*32 + k4];
      u64 s0 = splat2(a.x), s1 = splat2(a.y), s2 = splat2(a.z), s3 = splat2(a.w);
      acc[i][0] = ffma2(s0, b[0][0], acc[i][0]);
      acc[i][1] = ffma2(s0, b[0][1], acc[i][1]);
      acc[i][0] = ffma2(s1, b[1][0], acc[i][0]);
      acc[i][1] = ffma2(s1, b[1][1], acc[i][1]);
      acc[i][0] = ffma2(s2, b[2][0], acc[i][0]);
      acc[i][1] = ffma2(s2, b[2][1], acc[i][1]);
      acc[i][0] = ffma2(s3, b[3][0], acc[i][0]);
      acc[i][1] = ffma2(s3, b[3][1], acc[i][1]);
    }
  }
}

__device__ __forceinline__ void ln_reduce_store(float s, float sq, float* sm,
                                                int tid, int b, int which){
  #pragma unroll
  for (int off = 16; off; off >>= 1){
    s  += __shfl_xor_sync(0xffffffffu, s,  off);
    sq += __shfl_xor_sync(0xffffffffu, sq, off);
  }
  __syncthreads();
  if ((tid & 31) == 0){ sm[tid>>5] = s; sm[8 + (tid>>5)] = sq; }
  __syncthreads();
  if (tid == 0){
    float S = 0.f, SQ = 0.f;
    #pragma unroll
    for (int w = 0; w < 8; w++){ S += sm[w]; SQ += sm[8+w]; }
    atomicAdd(&g_red[which][b][0], S);
    atomicAdd(&g_red[which][b][1], SQ);
  }
}

__device__ __forceinline__ void ln_params(int which, int b, float& mean, float& rstd){
  float s  = g_red[which][b][0];
  float sq = g_red[which][b][1];
  const float M = 131072.f;
  mean = s / M;
  float var = (sq - s*s/M) / (M - 1.f);
  rstd = rsqrtf(var + 1e-5f);
}

// ---------------- K1: QKV projections (+ zero g_red from block (0,0)) ------
__global__ void __launch_bounds__(256) qkv_kernel(const float* __restrict__ x,
    const float* __restrict__ Wq, const float* __restrict__ Wk,
    const float* __restrict__ Wv){
  extern __shared__ float sm[];
  float* As = sm;             // 64*128
  float* Ws = sm + 64*128;    // 128*128
  int row0 = blockIdx.x * 64;
  const float* W = (blockIdx.y==0) ? Wq : (blockIdx.y==1 ? Wk : Wv);
  float* outp    = (blockIdx.y==0) ? g_Q : (blockIdx.y==1 ? g_K : g_V);
  int tid = threadIdx.x;

  if (blockIdx.x == 0 && blockIdx.y == 0 && tid < 32)
    ((float*)g_red)[tid] = 0.f;

  #pragma unroll
  for (int rep = 0; rep < 8; rep++){
    int idx = rep*256 + tid;
    ((float4*)As)[idx] = ((const float4*)(x + (size_t)row0*128))[idx];
  }
  #pragma unroll
  for (int rep = 0; rep < 16; rep++){
    int idx = rep*256 + tid;               // Ws[e][j], j = h*32+k
    int e = idx >> 5, j4 = idx & 31;
    ((float4*)Ws)[idx] =
      *(const float4*)(W + ((j4>>3)<<12) + (e<<5) + ((j4&7)<<2));
  }
  __syncthreads();

  int tr = tid >> 5, lane = tid & 31;
  int r0 = tr*8, c0 = lane*4;
  u64 acc[8][2];
  #pragma unroll
  for (int i=0;i<8;i++){ acc[i][0]=splat2(0.f); acc[i][1]=splat2(0.f); }
  gemm_compute2(As, Ws, acc, r0, lane);
  #pragma unroll
  for (int i=0;i<8;i++){
    float c[4];
    unpack2(acc[i][0], c[0], c[1]); unpack2(acc[i][1], c[2], c[3]);
    *(float4*)(outp + (size_t)(row0+r0+i)*128 + c0) =
      make_float4(c[0],c[1],c[2],c[3]);
  }
}

// ---------------- K2: fused attention -------------------------------------
// grid (16, 8): blockIdx.x = 64-query tile, blockIdx.y = batch. 256 threads.
// Smat uses column permutation pi(mi) = 8*(mi&7) + (mi>>3) (involution) so
// score stores hit 16 banks instead of 4; stride 66 keeps rows 8B-aligned
// for float2 softmax/P reads. Softmax is permutation-invariant per row.
#define SM_ST 66
__global__ void __launch_bounds__(256,1) attn_kernel(
    const float* __restrict__ in2, float* __restrict__ out2,
    const float* __restrict__ Ws1, const float* __restrict__ bs1,
    const float* __restrict__ Ws2, const float* __restrict__ bs2){
  extern __shared__ float sm[];
  float* Qs      = sm;               // 64*128 XOR-swizzled (16B granule)
  float* Ks      = Qs + 8192;        // 64*128 XOR-swizzled
  float* Vs      = Ks + 8192;        // 64*128 plain
  float* Smat    = Vs + 8192;        // 4*64*SM_ST, pi-permuted columns
  float* alpha_s = Smat + 4*64*SM_ST;
  float* rsum_s  = alpha_s + 256;
  float* mw      = rsum_s + 256;     // 112 (8B aligned)

  int tid = threadIdx.x;
  int n0  = blockIdx.x * 64;
  int b   = blockIdx.y;

  if (tid < 64)       mw[tid] = Ws1[tid];
  else if (tid < 72)  mw[tid] = bs1[tid-64];
  else if (tid < 104) mw[tid] = Ws2[tid-72];
  else if (tid < 108) mw[tid] = bs2[tid-104];

  // MLP layer-1 weights in registers (smem-limited occupancy, regs free)
  u64 w1[8][4], b1[4];
  #pragma unroll
  for (int i=0;i<8;i++)
    #pragma unroll
    for (int jp=0;jp<4;jp++)
      w1[i][jp] = *(const u64*)(Ws1 + i*8 + 2*jp);
  #pragma unroll
  for (int jp=0;jp<4;jp++) b1[jp] = *(const u64*)(bs1 + 2*jp);

  // load Q tile (swizzled: k4 ^= (r>>3)&7)
  {
    const float* Qg = g_Q + ((size_t)(b*1024 + n0))*128;
    #pragma unroll
    for (int rep = 0; rep < 8; rep++){
      int idx = rep*256 + tid; int r = idx>>5, k4 = idx&31;
      float4 v = ((const float4*)Qg)[r*32 + k4];
      *(float4*)(Qs + r*128 + ((k4 ^ ((r>>3)&7))<<2)) = v;
    }
  }

  int h = tid >> 6, t = tid & 63;
  int s_ni0 = (t&7)*8, s_mi0 = (t>>3)*8;      // score micro-tile 8x8
  int p_ni0 = (t>>3)*8, p_k0  = (t&7)*4;      // PV / output micro-tile
  int qsw = t & 7, ksw = t >> 3;

  u64 O2[8][2];
  #pragma unroll
  for (int i=0;i<8;i++){ O2[i][0]=splat2(0.f); O2[i][1]=splat2(0.f); }
  float rmax = -1e30f, rsum = 0.f;

  const float* in2b = in2  + (size_t)b*1048576;
  float*       o2b  = out2 + (size_t)b*1048576;

  for (int it = 0; it < 16; it++){
    int m0 = it*64;
    __syncthreads();   // prev PV / Smat reads done before overwrite
    {
      const float* Kg = g_K + ((size_t)(b*1024 + m0))*128;
      const float* Vg = g_V + ((size_t)(b*1024 + m0))*128;
      #pragma unroll
      for (int rep = 0; rep < 8; rep++){
        int idx = rep*256 + tid; int r = idx>>5, k4 = idx&31;
        float4 kv = ((const float4*)Kg)[r*32 + k4];
        *(float4*)(Ks + r*128 + ((k4 ^ ((r>>3)&7))<<2)) = kv;
        float4 vv = ((const float4*)Vg)[r*32 + k4];
        *(float4*)(Vs + r*128 + (k4<<2)) = vv;
      }
    }
    __syncthreads();

    // ---- scores: S[h][ni][mi] = Q_h . K_h ; float4 operand loads ---------
    {
      u64 acc2[8][4];   // [row i][col pair jp]
      #pragma unroll
      for (int i=0;i<8;i++)
        #pragma unroll
        for (int jp=0;jp<4;jp++) acc2[i][jp] = splat2(0.f);
      #pragma unroll
      for (int kk4 = 0; kk4 < 8; kk4++){
        int kidx = (h<<3) + kk4;
        float4 a4[8], b4[8];
        #pragma unroll
        for (int i=0;i<8;i++)
          a4[i] = *(const float4*)(Qs + (s_ni0+i)*128 + ((kidx ^ qsw)<<2));
        #pragma unroll
        for (int j=0;j<8;j++)
          b4[j] = *(const float4*)(Ks + (s_mi0+j)*128 + ((kidx ^ ksw)<<2));
        #pragma unroll
        for (int kk=0; kk<4; kk++){
          u64 bp[4];
          #pragma unroll
          for (int jp=0;jp<4;jp++)
            bp[jp] = pack2(((const float*)&b4[2*jp])[kk],
                           ((const float*)&b4[2*jp+1])[kk]);
          #pragma unroll
          for (int i=0;i<8;i++){
            u64 sa = splat2(((const float*)&a4[i])[kk]);
            #pragma unroll
            for (int jp=0;jp<4;jp++) acc2[i][jp] = ffma2(sa, bp[jp], acc2[i][jp]);
          }
        }
      }
      // store with pi: column (s_mi0 + j) = 8*ksw + j  ->  pi = 8*j + ksw
      #pragma unroll
      for (int i=0;i<8;i++){
        float* Sr = Smat + ((h<<6) + s_ni0 + i)*SM_ST;
        float c[8];
        #pragma unroll
        for (int jp=0;jp<4;jp++) unpack2(acc2[i][jp], c[2*jp], c[2*jp+1]);
        #pragma unroll
        for (int j=0;j<8;j++) Sr[(j<<3) + ksw] = c[j];
      }
    }
    __syncthreads();

    // ---- 8->8(relu)->4 MLP, fused input2 read + passthrough write --------
    {
      int ni  = tid >> 2;
      int mi0 = (tid & 3) * 4;
      const float* p0 = in2b + ((size_t)(n0+ni)<<10) + m0;
      float*       q0 = o2b  + ((size_t)(n0+ni)<<10) + m0;
      #pragma unroll
      for (int m4 = 0; m4 < 4; m4++){
        int mbase = mi0 + m4*16;
        float4 t2[4];
        #pragma unroll
        for (int hh=0; hh<4; hh++){
          t2[hh] = *(const float4*)(p0 + (size_t)hh*8388608 + mbase);
          *(float4*)(q0 + (size_t)hh*8388608 + mbase) = t2[hh];
        }
        #pragma unroll
        for (int e=0; e<4; e++){
          int mi = mbase + e;
          int smi = ((mi & 7) << 3) + (mi >> 3);   // pi(mi)
          float x[8];
          #pragma unroll
          for (int hh=0; hh<4; hh++) x[hh] = Smat[((hh<<6)+ni)*SM_ST + smi];
          x[4] = ((float*)&t2[0])[e]; x[5] = ((float*)&t2[1])[e];
          x[6] = ((float*)&t2[2])[e]; x[7] = ((float*)&t2[3])[e];
          u64 z2[4] = { b1[0], b1[1], b1[2], b1[3] };
          #pragma unroll
          for (int i=0;i<8;i++){
            u64 sx = splat2(x[i]);
            #pragma unroll
            for (int jp=0;jp<4;jp++) z2[jp] = ffma2(sx, w1[i][jp], z2[jp]);
          }
          u64 y2[2];
          y2[0] = *(const u64*)(mw+104);
          y2[1] = *(const u64*)(mw+106);
          #pragma unroll
          for (int jp=0;jp<4;jp++){
            float zl, zh; unpack2(z2[jp], zl, zh);
            zl = fmaxf(zl, 0.f); zh = fmaxf(zh, 0.f);
            u64 sl = splat2(zl), sh = splat2(zh);
            int j0 = 2*jp, j1 = 2*jp+1;
            y2[0] = ffma2(sl, *(const u64*)(mw + 72 + j0*4),     y2[0]);
            y2[1] = ffma2(sl, *(const u64*)(mw + 72 + j0*4 + 2), y2[1]);
            y2[0] = ffma2(sh, *(const u64*)(mw + 72 + j1*4),     y2[0]);
            y2[1] = ffma2(sh, *(const u64*)(mw + 72 + j1*4 + 2), y2[1]);
          }
          float y[4];
          unpack2(y2[0], y[0], y[1]); unpack2(y2[1], y[2], y[3]);
          #pragma unroll
          for (int hh=0;hh<4;hh++)
            Smat[((hh<<6)+ni)*SM_ST + smi] = y[hh]*LOG2E;
        }
      }
    }
    __syncthreads();

    // ---- online softmax (1 thread per (h,ni) row; pi-invariant) ----------
    {
      float* Sr = Smat + tid*SM_ST;    // 8B-aligned (66*4B = 264B)
      float mt = -1e30f;
      #pragma unroll 8
      for (int q=0; q<32; q++){
        float2 v = *(const float2*)(Sr + 2*q);
        mt = fmaxf(mt, fmaxf(v.x, v.y));
      }
      float mnew = fmaxf(rmax, mt);
      float al = fexp2(rmax - mnew);
      float st = 0.f;
      #pragma unroll 8
      for (int q=0; q<32; q++){
        float2 v = *(const float2*)(Sr + 2*q);
        float pp0 = fexp2(v.x - mnew);
        float pp1 = fexp2(v.y - mnew);
        *(float2*)(Sr + 2*q) = make_float2(pp0, pp1);
        st += pp0 + pp1;
      }
      rsum = rsum*al + st;
      rmax = mnew;
      alpha_s[tid] = al;
      rsum_s[tid]  = rsum;
    }
    __syncthreads();

    // ---- rescale + P @ V; P read as float2 pairs (linear c) --------------
    // linear index c maps to column mi = pi(c); pi(c+1) = pi(c)+8 for even c.
    {
      #pragma unroll
      for (int i=0;i<8;i++){
        u64 al = splat2(alpha_s[(h<<6) + p_ni0 + i]);
        O2[i][0] = fmul2(O2[i][0], al);
        O2[i][1] = fmul2(O2[i][1], al);
      }
      const float* pbase = Smat + ((h<<6)+p_ni0)*SM_ST;
      const float* vbase = Vs + (h<<5) + p_k0;
      #pragma unroll 4
      for (int c2 = 0; c2 < 32; c2++){
        int c = 2*c2;
        int mi0 = ((c & 7) << 3) + (c >> 3);   // pi(c)
        ulonglong2 vv0 = *(const ulonglong2*)(vbase + mi0*128);
        ulonglong2 vv1 = *(const ulonglong2*)(vbase + (mi0+8)*128);
        #pragma unroll
        for (int i=0;i<8;i++){
          float2 pp = *(const float2*)(pbase + i*SM_ST + c);
          u64 s0 = splat2(pp.x), s1 = splat2(pp.y);
          O2[i][0] = ffma2(s0, vv0.x, O2[i][0]);
          O2[i][1] = ffma2(s0, vv0.y, O2[i][1]);
          O2[i][0] = ffma2(s1, vv1.x, O2[i][0]);
          O2[i][1] = ffma2(s1, vv1.y, O2[i][1]);
        }
      }
    }
  }

  // final normalize + write heads output
  float* Og = g_O + ((size_t)(b*1024 + n0))*128;
  #pragma unroll
  for (int i=0;i<8;i++){
    float inv = 1.f / rsum_s[(h<<6) + p_ni0 + i];
    float c[4];
    unpack2(O2[i][0], c[0], c[1]); unpack2(O2[i][1], c[2], c[3]);
    *(float4*)(Og + (size_t)(p_ni0+i)*128 + (h<<5) + p_k0) =
      make_float4(c[0]*inv, c[1]*inv, c[2]*inv, c[3]*inv);
  }
}

// ---------------- K3: out-projection + residual + LN0 sums -----------------
__global__ void __launch_bounds__(256) outproj_kernel(
    const float* __restrict__ input1, const float* __restrict__ Wout){
  extern __shared__ float sm[];
  float* As = sm; float* Ws = sm + 64*128;
  int row0 = blockIdx.x * 64; int tid = threadIdx.x;
  #pragma unroll
  for (int rep=0; rep<8; rep++){
    int idx = rep*256 + tid;
    ((float4*)As)[idx] = ((const float4*)(g_O + (size_t)row0*128))[idx];
  }
  #pragma unroll
  for (int rep=0; rep<16; rep++){
    int idx = rep*256 + tid;
    ((float4*)Ws)[idx] = ((const float4*)Wout)[idx];
  }
  __syncthreads();
  int tr = tid>>5, lane = tid&31, r0 = tr*8, c0 = lane*4;
  u64 acc[8][2];
  #pragma unroll
  for (int i=0;i<8;i++){ acc[i][0]=splat2(0.f); acc[i][1]=splat2(0.f); }
  gemm_compute2(As, Ws, acc, r0, lane);
  float s=0.f, sq=0.f;
  #pragma unroll
  for (int i=0;i<8;i++){
    float c[4];
    unpack2(acc[i][0], c[0], c[1]); unpack2(acc[i][1], c[2], c[3]);
    float4 res = *(const float4*)(input1 + (size_t)(row0+r0+i)*128 + c0);
    float4 o = make_float4(c[0]+res.x, c[1]+res.y, c[2]+res.z, c[3]+res.w);
    *(float4*)(g_Y + (size_t)(row0+r0+i)*128 + c0) = o;
    s  += o.x+o.y+o.z+o.w;
    sq += o.x*o.x+o.y*o.y+o.z*o.z+o.w*o.w;
  }
  ln_reduce_store(s, sq, sm, tid, row0>>10, 0);
}

// ---------------- K4: FF1 (inline LN0 of g_Y, relu) ------------------------
__global__ void __launch_bounds__(256) ff1_kernel(const float* __restrict__ Wff1){
  extern __shared__ float sm[];
  float* As = sm; float* Ws = sm + 64*128;
  int row0 = blockIdx.x * 64, ct = blockIdx.y, tid = threadIdx.x;
  float mean, rstd; ln_params(0, row0>>10, mean, rstd);
  #pragma unroll
  for (int rep=0; rep<8; rep++){
    int idx = rep*256 + tid;
    float4 v = ((const float4*)(g_Y + (size_t)row0*128))[idx];
    v.x=(v.x-mean)*rstd; v.y=(v.y-mean)*rstd;
    v.z=(v.z-mean)*rstd; v.w=(v.w-mean)*rstd;
    ((float4*)As)[idx] = v;
  }
  #pragma unroll
  for (int rep=0; rep<16; rep++){
    int idx = rep*256 + tid;
    int e = idx>>5, c4 = idx&31;
    ((float4*)Ws)[idx] = *(const float4*)(Wff1 + (size_t)e*512 + ct*128 + c4*4);
  }
  __syncthreads();
  int tr = tid>>5, lane = tid&31, r0 = tr*8, c0 = lane*4;
  u64 acc[8][2];
  #pragma unroll
  for (int i=0;i<8;i++){ acc[i][0]=splat2(0.f); acc[i][1]=splat2(0.f); }
  gemm_compute2(As, Ws, acc, r0, lane);
  #pragma unroll
  for (int i=0;i<8;i++){
    float c[4];
    unpack2(acc[i][0], c[0], c[1]); unpack2(acc[i][1], c[2], c[3]);
    float4 o = make_float4(fmaxf(c[0],0.f), fmaxf(c[1],0.f),
                           fmaxf(c[2],0.f), fmaxf(c[3],0.f));
    *(float4*)(g_FF + (size_t)(row0+r0+i)*512 + ct*128 + c0) = o;
  }
}

// ---------------- K5: FF2 + residual (inline LN0) + LN1 sums ---------------
__global__ void __launch_bounds__(256) ff2_kernel(const float* __restrict__ Wff2){
  extern __shared__ float sm[];
  float* As = sm; float* Ws = sm + 64*128;
  int row0 = blockIdx.x * 64, tid = threadIdx.x;
  float mean, rstd; ln_params(0, row0>>10, mean, rstd);
  int tr = tid>>5, lane = tid&31, r0 = tr*8, c0 = lane*4;
  u64 acc[8][2];
  #pragma unroll
  for (int i=0;i<8;i++){ acc[i][0]=splat2(0.f); acc[i][1]=splat2(0.f); }
  for (int ch = 0; ch < 4; ch++){
    __syncthreads();
    #pragma unroll
    for (int rep=0; rep<8; rep++){
      int idx = rep*256 + tid; int r = idx>>5, k4 = idx&31;
      ((float4*)As)[idx] =
        *(const float4*)(g_FF + (size_t)(row0+r)*512 + ch*128 + k4*4);
    }
    #pragma unroll
    for (int rep=0; rep<16; rep++){
      int idx = rep*256 + tid;
      ((float4*)Ws)[idx] = ((const float4*)(Wff2 + (size_t)ch*16384))[idx];
    }
    __syncthreads();
    gemm_compute2(As, Ws, acc, r0, lane);
  }
  float s=0.f, sq=0.f;
  #pragma unroll
  for (int i=0;i<8;i++){
    float c[4];
    unpack2(acc[i][0], c[0], c[1]); unpack2(acc[i][1], c[2], c[3]);
    float4 res = *(const float4*)(g_Y + (size_t)(row0+r0+i)*128 + c0);
    res.x=(res.x-mean)*rstd; res.y=(res.y-mean)*rstd;
    res.z=(res.z-mean)*rstd; res.w=(res.w-mean)*rstd;
    float4 o = make_float4(c[0]+res.x, c[1]+res.y, c[2]+res.z, c[3]+res.w);
    *(float4*)(g_Y + (size_t)(row0+r0+i)*128 + c0) = o;   // own rows only
    s  += o.x+o.y+o.z+o.w;
    sq += o.x*o.x+o.y*o.y+o.z*o.z+o.w*o.w;
  }
  ln_reduce_store(s, sq, sm, tid, row0>>10, 1);
}

// ---------------- K6: final global LayerNorm (ddof=1) ----------------------
__global__ void __launch_bounds__(256) norm_kernel(float* __restrict__ extout){
  int id = blockIdx.x*256 + threadIdx.x;          // float4 index
  int b = (id*4) >> 17;
  float mean, rstd; ln_params(1, b, mean, rstd);
  float4 v = ((const float4*)g_Y)[id];
  v.x = (v.x-mean)*rstd; v.y = (v.y-mean)*rstd;
  v.z = (v.z-mean)*rstd; v.w = (v.w-mean)*rstd;
  ((float4*)extout)[id] = v;
}

// ---------------- launcher --------------------------------------------------
extern "C" void kernel_launch(void* const* d_in, const int* in_sizes, int n_in,
                              void* d_out, int out_size){
  const float* input1 = (const float*)d_in[0];
  const float* input2 = (const float*)d_in[1];
  const float* Wq  = (const float*)d_in[2];
  const float* Wk  = (const float*)d_in[3];
  const float* Wv  = (const float*)d_in[4];
  const float* Wo  = (const float*)d_in[5];
  const float* Ws1 = (const float*)d_in[6];
  const float* bs1 = (const float*)d_in[7];
  const float* Ws2 = (const float*)d_in[8];
  const float* bs2 = (const float*)d_in[9];
  const float* Wff1 = (const float*)d_in[10];
  const float* Wff2 = (const float*)d_in[11];
  float* out1 = (float*)d_out;
  float* out2 = out1 + 8*1024*128;      // input2 passthrough region

  const int GEMM_SMEM = (64*128 + 128*128)*4;                         // 98304
  const int ATTN_SMEM = (3*8192 + 4*64*SM_ST + 256 + 256 + 112)*4;    // 168832

  cudaFuncSetAttribute(qkv_kernel,     cudaFuncAttributeMaxDynamicSharedMemorySize, GEMM_SMEM);
  cudaFuncSetAttribute(attn_kernel,    cudaFuncAttributeMaxDynamicSharedMemorySize, ATTN_SMEM);
  cudaFuncSetAttribute(outproj_kernel, cudaFuncAttributeMaxDynamicSharedMemorySize, GEMM_SMEM);
  cudaFuncSetAttribute(ff1_kernel,     cudaFuncAttributeMaxDynamicSharedMemorySize, GEMM_SMEM);
  cudaFuncSetAttribute(ff2_kernel,     cudaFuncAttributeMaxDynamicSharedMemorySize, GEMM_SMEM);

  qkv_kernel<<<dim3(128,3), 256, GEMM_SMEM>>>(input1, Wq, Wk, Wv);
  attn_kernel<<<dim3(16,8), 256, ATTN_SMEM>>>(input2, out2, Ws1, bs1, Ws2, bs2);
  outproj_kernel<<<128, 256, GEMM_SMEM>>>(input1, Wo);
  ff1_kernel<<<dim3(128,4), 256, GEMM_SMEM>>>(Wff1);
  ff2_kernel<<<128, 256, GEMM_SMEM>>>(Wff2);
  norm_kernel<<<1024, 256>>>(out1);
}